// round 17
// baseline (speedup 1.0000x reference)
#include <cuda_runtime.h>
#include <math.h>

// ---------------------------------------------------------------------------
// GNNLoss fused single-kernel (R17): 32 warps x 4-deep software pipeline.
//
// Sweep history: (warps x lookahead) products tried: 32x2=64 (42.7us, best),
// 24x2=48 (45.1), 16x4=64 (47.9). Never tried: high warps AND deep lookahead
// -- blocked by 12-reg stages spilling at the 64-reg/1024-thr cap. R17 uses
// 2-edge stages (6 regs each): 4-deep pipeline fits in ~52 regs at 1024
// threads -> 32 warps x 4 stages, 12 independent LDG.64 in flight per warp,
// ~600cyc chain covered structurally.
//
// key[node]  = (pi==0) ? 0 : (batch<<10)|pi     (u16 exact)
// hash[node] = (key==0) ? 0 : (key % 255) + 1   (u8 filter, 200KB smem)
// target: hash mismatch -> 0; both zero -> 0; else exact u16 key compare
// (~0.43% of edges) in one warp-uniform predicated region.
// ---------------------------------------------------------------------------

#define MAX_NODES  262144
#define MAX_BLOCKS 512
#define NTHREADS   1024

__device__ __align__(16) unsigned short g_keys[MAX_NODES];
__device__ __align__(16) unsigned char  g_hash[MAX_NODES];
__device__ float g_part_es[MAX_BLOCKS];
__device__ int   g_part_ec[MAX_BLOCKS];
__device__ float g_part_ns[MAX_BLOCKS];
__device__ int   g_part_nc[MAX_BLOCKS];
__device__ unsigned int g_bar0;   // zero-init; reset by block 0 each run
__device__ unsigned int g_bar1;

__device__ __forceinline__ float rcp_approx(float x) {
    float y;
    asm("rcp.approx.f32 %0, %1;" : "=f"(y) : "f"(x));
    return y;
}

__device__ __forceinline__ float focal_term(float x, bool t) {
    float a  = fabsf(x);
    float em = __expf(-a);             // MUFU.EX2 (+mul)
    float w  = 1.0f + em;              // w in [1,2]
    float L  = __logf(w);              // MUFU.LG2 (+mul)
    float q  = em * rcp_approx(w);     // 1 - sigmoid(|x|), MUFU.RCP ~1ulp
    bool  m  = ((x >= 0.0f) == t);
    float omp = m ? q : (1.0f - q);    // 1 - p_t
    float ce  = m ? L : (a + L);       // BCE-with-logits
    float at  = t ? 0.25f : 0.75f;     // ALPHA=0.25
    return at * ce * omp * omp;        // GAMMA=2
}

// block reduction of (float, int) -> one slot per block
__device__ __forceinline__ void block_reduce_store(float s, int c,
                                                   float* ps, int* pc) {
    #pragma unroll
    for (int o = 16; o > 0; o >>= 1) {
        s += __shfl_down_sync(0xFFFFFFFFu, s, o);
        c += __shfl_down_sync(0xFFFFFFFFu, c, o);
    }
    __shared__ float sh_s[32];
    __shared__ int   sh_c[32];
    int lane = threadIdx.x & 31;
    int wid  = threadIdx.x >> 5;
    if (lane == 0) { sh_s[wid] = s; sh_c[wid] = c; }
    __syncthreads();
    int nw = (blockDim.x + 31) >> 5;
    if (wid == 0) {
        s = (lane < nw) ? sh_s[lane] : 0.0f;
        c = (lane < nw) ? sh_c[lane] : 0;
        #pragma unroll
        for (int o = 16; o > 0; o >>= 1) {
            s += __shfl_down_sync(0xFFFFFFFFu, s, o);
            c += __shfl_down_sync(0xFFFFFFFFu, c, o);
        }
        if (lane == 0) { ps[blockIdx.x] = s; pc[blockIdx.x] = c; }
    }
    __syncthreads();
}

__device__ __forceinline__ void grid_barrier(unsigned int* bar, int nb) {
    __syncthreads();
    if (threadIdx.x == 0) {
        __threadfence();
        atomicAdd(bar, 1u);
        while (*(volatile unsigned int*)bar < (unsigned int)nb) { }
    }
    __syncthreads();
    __threadfence();
}

__global__ void __launch_bounds__(NTHREADS, 1)
fused_kernel(const float* __restrict__ edge_logits,
             const float* __restrict__ node_logits,
             const int*   __restrict__ batch,
             const int*   __restrict__ pinst,
             const int*   __restrict__ src,
             const int*   __restrict__ dst,
             int E, int N, int nvec2,
             float* __restrict__ out) {
    extern __shared__ unsigned char sh[];
    int tid     = threadIdx.x;
    int nb      = gridDim.x;
    int gtid    = blockIdx.x * blockDim.x + tid;
    int gstride = nb * blockDim.x;

    // ---- phase 1: nodes (build key + hash tables, node loss/acc) ----
    float ns = 0.0f; int nc = 0;
    for (int i = gtid; i < N; i += gstride) {
        int p = pinst[i];
        int b = batch[i];
        unsigned short key = (p == 0) ? (unsigned short)0
                                      : (unsigned short)((b << 10) | p);
        g_keys[i] = key;
        g_hash[i] = (key == 0) ? (unsigned char)0
                               : (unsigned char)((key % 255) + 1);
        float x = node_logits[i];
        bool  t = (p != 0);
        ns += focal_term(x, t);
        nc += ((x > 0.0f) == t) ? 1 : 0;
    }
    block_reduce_store(ns, nc, g_part_ns, g_part_nc);

    grid_barrier(&g_bar0, nb);   // tables complete, visible in L2

    // ---- broadcast hash table into shared memory ----
    int nw4 = (N + 15) >> 4;
    const uint4* hv = (const uint4*)g_hash;
    uint4* s4 = (uint4*)sh;
    for (int i = tid; i < nw4; i += NTHREADS) s4[i] = hv[i];
    __syncthreads();

    // ---- phase 2: edges, 2-edge stages, 4-deep rotating pipeline ----
    const float2* el2 = (const float2*)edge_logits;
    const int2*   sv2 = (const int2*)src;
    const int2*   dv2 = (const int2*)dst;
    float es = 0.0f; int ec = 0;

    float2 x0, x1, x2, x3;
    int2   s0, s1, s2, s3, d0, d1, d2, d3;

    // prologue: fill 4 stages (guarded)
    {
        int i0 = gtid, i1 = i0 + gstride, i2 = i1 + gstride, i3 = i2 + gstride;
        if (i0 < nvec2) { x0 = __ldcs(&el2[i0]); s0 = __ldcs(&sv2[i0]); d0 = __ldcs(&dv2[i0]); }
        if (i1 < nvec2) { x1 = __ldcs(&el2[i1]); s1 = __ldcs(&sv2[i1]); d1 = __ldcs(&dv2[i1]); }
        if (i2 < nvec2) { x2 = __ldcs(&el2[i2]); s2 = __ldcs(&sv2[i2]); d2 = __ldcs(&dv2[i2]); }
        if (i3 < nvec2) { x3 = __ldcs(&el2[i3]); s3 = __ldcs(&sv2[i3]); d3 = __ldcs(&dv2[i3]); }
    }

    int ic = gtid;                 // consume index (stage 0 is valid iff ic<nvec2)
    int ip = gtid + 4 * gstride;   // refill index
    while (ic < nvec2) {
        // take stage 0
        float2 xc = x0; int2 sc = s0, dc = d0;

        // rotate + refill (refill LDGs issued early, overlap math below)
        x0 = x1; s0 = s1; d0 = d1;
        x1 = x2; s1 = s2; d1 = d2;
        x2 = x3; s2 = s3; d2 = d3;
        if (ip < nvec2) { x3 = __ldcs(&el2[ip]); s3 = __ldcs(&sv2[ip]); d3 = __ldcs(&dv2[ip]); }
        ip += gstride;

        // hash gathers (LDS latency overlaps focal math)
        unsigned int h0s = sh[sc.x], h0d = sh[dc.x];
        unsigned int h1s = sh[sc.y], h1d = sh[dc.y];
        bool n0 = (h0s == h0d) & (h0s != 0u);
        bool n1 = (h1s == h1d) & (h1s != 0u);

        // rare exact checks: one warp-uniform region, per-lane predication
        unsigned short k0s = 0, k0d = 0, k1s = 0, k1d = 0;
        unsigned int amask = __activemask();
        if (__any_sync(amask, n0 | n1)) {
            k0s = n0 ? __ldg(&g_keys[sc.x]) : k0s;
            k0d = n0 ? __ldg(&g_keys[dc.x]) : k0d;
            k1s = n1 ? __ldg(&g_keys[sc.y]) : k1s;
            k1d = n1 ? __ldg(&g_keys[dc.y]) : k1d;
        }
        bool t0 = n0 & (k0s == k0d);
        bool t1 = n1 & (k1s == k1d);

        es += focal_term(xc.x, t0);
        es += focal_term(xc.y, t1);
        ec += ((xc.x > 0.0f) == t0) ? 1 : 0;
        ec += ((xc.y > 0.0f) == t1) ? 1 : 0;

        ic += gstride;
    }

    // tail edges (E % 2, or whole range if vec path disabled)
    if (blockIdx.x == 0 && tid == 0) {
        for (int e = nvec2 << 1; e < E; e++) {
            int sidx = src[e], didx = dst[e];
            unsigned short ks = g_keys[sidx], kd = g_keys[didx];
            bool t = (ks == kd) && (ks != 0);
            float xe = edge_logits[e];
            es += focal_term(xe, t);
            ec += ((xe > 0.0f) == t) ? 1 : 0;
        }
    }
    block_reduce_store(es, ec, g_part_es, g_part_ec);

    // ---- final barrier; block 0 reduces partials and writes outputs ----
    if (tid == 0) { __threadfence(); atomicAdd(&g_bar1, 1u); }
    if (blockIdx.x != 0) return;
    if (tid == 0) {
        while (*(volatile unsigned int*)&g_bar1 < (unsigned int)nb) { }
    }
    __syncthreads();
    __threadfence();

    if (tid < 32) {
        double des = 0.0, dns = 0.0;
        int iec = 0, inc = 0;
        for (int k = tid; k < nb; k += 32) {
            des += (double)g_part_es[k];
            dns += (double)g_part_ns[k];
            iec += g_part_ec[k];
            inc += g_part_nc[k];
        }
        #pragma unroll
        for (int o = 16; o > 0; o >>= 1) {
            des += __shfl_down_sync(0xFFFFFFFFu, des, o);
            dns += __shfl_down_sync(0xFFFFFFFFu, dns, o);
            iec += __shfl_down_sync(0xFFFFFFFFu, iec, o);
            inc += __shfl_down_sync(0xFFFFFFFFu, inc, o);
        }
        if (tid == 0) {
            float edge_loss = (float)(des / (double)E);
            float node_loss = (float)(dns / (double)N);
            out[0] = edge_loss + node_loss;  // EDGE_W = NODE_W = 1
            out[1] = edge_loss;
            out[2] = node_loss;
            out[3] = (float)((double)iec / (double)E);
            out[4] = (float)((double)inc / (double)N);
            g_bar0 = 0;                      // reset for next graph replay
            g_bar1 = 0;
        }
    }
}

extern "C" void kernel_launch(void* const* d_in, const int* in_sizes, int n_in,
                              void* d_out, int out_size) {
    const float* edge_logits = (const float*)d_in[0];
    const float* node_logits = (const float*)d_in[1];
    const int*   batch       = (const int*)d_in[2];
    const int*   pinst       = (const int*)d_in[3];
    const int*   edge_index  = (const int*)d_in[4];

    int E = in_sizes[0];
    int N = in_sizes[1];
    const int* src = edge_index;
    const int* dst = edge_index + E;
    float* out = (float*)d_out;

    // 2-edge vec path requires E even (dst pointer 8B-aligned)
    int nvec2 = ((E & 1) == 0) ? (E >> 1) : 0;

    int smem_bytes = ((N + 15) >> 4) << 4;   // 8-bit hash table, 16B padded
    cudaFuncSetAttribute(fused_kernel,
                         cudaFuncAttributeMaxDynamicSharedMemorySize,
                         smem_bytes);

    int sm_count = 148;
    cudaDeviceGetAttribute(&sm_count, cudaDevAttrMultiProcessorCount, 0);

    // size the grid by ACTUAL occupancy so the grid barrier cannot deadlock
    int per_sm = 1;
    cudaOccupancyMaxActiveBlocksPerMultiprocessor(&per_sm, fused_kernel,
                                                  NTHREADS, smem_bytes);
    if (per_sm < 1) per_sm = 1;
    int nblocks = sm_count * per_sm;
    if (nblocks > MAX_BLOCKS) nblocks = MAX_BLOCKS;

    fused_kernel<<<nblocks, NTHREADS, smem_bytes>>>(edge_logits, node_logits,
                                                    batch, pinst, src, dst,
                                                    E, N, nvec2, out);
}